// round 12
// baseline (speedup 1.0000x reference)
#include <cuda_runtime.h>
#include <cstdint>

#define Bn   16
#define Tn   32
#define INn  112
#define Hn   512
#define NGn  7
#define En   409      // int(0.8*512)
#define EXn  410      // H - round(0.2*512)
#define AWc   0.02f
#define OMAWc 0.98f
#define AXc   0.2f
#define OMAXc 0.8f
#define DTc   0.02f

struct __align__(16) SM {
    float wh[64 * Hn];      // plastic recurrent weights (SMEM now)     131072 B
    float wx[64 * INn];     // plastic input weights                     28672 B
    float awbx[64 * INn];   // alpha_w * relu(w_x2h)                     28672 B
    float wa[NGn * 64];     // plastic attn weights, THIS CTA's columns   1792 B
    float awba[NGn * 64];   //                                            1792 B
    float effc[Hn];         // relu(w_h2o[rank]) * exist                  2048 B
    float effv[Hn];         // relu(w_h2v) * exist                        2048 B
    float o[4][Hn];         // out(tau) lives in o[tau & 3]               8192 B
    float rowdat[64 * 4];   // per local row: {bh, awbd, wd, pad}         1024 B
    float plog[2][8][8];    // partial logits [parity][src_rank][group]    512 B
    float battn[8];
    float Rs[Tn];
};

// decay target alpha_w * relu(w_h2h), 16 MB, L2-resident; written at init.
__device__ float g_awbh[Bn * Hn * Hn];

__device__ __forceinline__ float warp_sum(float v) {
    v += __shfl_xor_sync(0xffffffffu, v, 16);
    v += __shfl_xor_sync(0xffffffffu, v, 8);
    v += __shfl_xor_sync(0xffffffffu, v, 4);
    v += __shfl_xor_sync(0xffffffffu, v, 2);
    v += __shfl_xor_sync(0xffffffffu, v, 1);
    return v;
}
__device__ __forceinline__ unsigned int smem_u32(const void* p) {
    unsigned int a;
    asm("{ .reg .u64 t; cvta.to.shared.u64 t, %1; cvt.u32.u64 %0, t; }" : "=r"(a) : "l"(p));
    return a;
}
__device__ __forceinline__ void st_clu(unsigned int laddr, int rank, float v) {
    unsigned int ra;
    asm volatile("mapa.shared::cluster.u32 %0, %1, %2;" : "=r"(ra) : "r"(laddr), "r"(rank));
    asm volatile("st.shared::cluster.f32 [%0], %1;" :: "r"(ra), "f"(v) : "memory");
}
// tanh(relu(x)) with fast exp/div; exact saturation beyond 15
__device__ __forceinline__ float tanh_relu_fast(float x) {
    float xr = fminf(fmaxf(x, 0.f), 15.f);
    float e2 = __expf(2.f * xr);
    return __fdividef(e2 - 1.f, e2 + 1.f);
}

__global__ void __launch_bounds__(512, 1) __cluster_dims__(8, 1, 1)
rnn_kernel(const float* __restrict__ x, const float* __restrict__ R,
           const float* __restrict__ w_x2h, const float* __restrict__ w_h2h,
           const float* __restrict__ b_h2h, const float* __restrict__ w_attn,
           const float* __restrict__ b_attn, const float* __restrict__ w_h2o,
           const float* __restrict__ w_h2v, const float* __restrict__ kappa,
           float* __restrict__ yout)
{
    extern __shared__ __align__(16) char smraw[];
    SM& s = *reinterpret_cast<SM*>(smraw);

    const int tid  = threadIdx.x;
    const int w    = tid >> 5;
    const int l    = tid & 31;
    const int rank = blockIdx.x & 7;
    const int b    = blockIdx.x >> 3;
    const int rl0  = w * 4;            // local row base in CTA (0..60)
    const int row0 = rank * 64 + rl0;  // global row base
    const int lk   = l * 4;            // column base within a 128-block
    const int g    = (w < NGn) ? w : 0;   // attention group for wa warps

    // ---------------- init ----------------
    if (tid < 8)   s.battn[tid] = (tid < NGn) ? b_attn[tid] : 0.f;
    if (tid < Tn)  s.Rs[tid]    = R[tid * Bn + b];
    if (tid < 128) reinterpret_cast<float*>(s.plog)[tid] = 0.f;
    s.o[3][tid] = 0.f;                 // out(-1) = 0
    if (tid < NGn * 64) {              // this CTA's wa columns
        const int gg = tid >> 6, col = tid & 63;
        const float v = fmaxf(w_attn[gg * Hn + rank * 64 + col], 0.f);
        s.wa[tid] = v; s.awba[tid] = AWc * v;
    }
    s.effc[tid] = (tid < EXn) ? fmaxf(w_h2o[rank * Hn + tid], 0.f) : 0.f;
    s.effv[tid] = (tid < EXn) ? fmaxf(w_h2v[tid], 0.f) : 0.f;
    if (l < 4) {
        const int row = row0 + l;
        const float dv = fmaxf(w_h2h[row * Hn + row], 0.f);
        s.rowdat[(rl0 + l) * 4 + 0] = b_h2h[row];
        s.rowdat[(rl0 + l) * 4 + 1] = AWc * dv;
        s.rowdat[(rl0 + l) * 4 + 2] = dv;
        s.rowdat[(rl0 + l) * 4 + 3] = 0.f;
    }

    // uniform kappa scalars (registers — R10 style)
    const float k00 = kappa[0], k01 = kappa[1], k10 = kappa[2], k11 = kappa[3];
    const float kinAt = kappa[4 + 2 * (l >> 2)];
    const float kinBt = kappa[5 + 2 * (l >> 2)];
    const float kfb = kappa[18 + g / 3];

    // wh -> SMEM; awbh -> device-global scratch (same thread later RMWs
    // exactly the elements it writes here: no cross-thread ordering needed).
    #pragma unroll
    for (int r = 0; r < 4; r++) {
        const int row = row0 + r;
        #pragma unroll
        for (int c4 = 0; c4 < 4; c4++) {
            const int j0 = c4 * 128 + lk;
            float4 v = *reinterpret_cast<const float4*>(&w_h2h[row * Hn + j0]);
            v.x = fmaxf(v.x, 0.f); v.y = fmaxf(v.y, 0.f);
            v.z = fmaxf(v.z, 0.f); v.w = fmaxf(v.w, 0.f);
            *reinterpret_cast<float4*>(&s.wh[(rl0 + r) * Hn + j0]) = v;
            *reinterpret_cast<float4*>(&g_awbh[((size_t)b * Hn + row) * Hn + j0]) =
                make_float4(AWc*v.x, AWc*v.y, AWc*v.z, AWc*v.w);
        }
        if (l < 28) {
            float4 v = *reinterpret_cast<const float4*>(&w_x2h[row * INn + lk]);
            v.x = fmaxf(v.x, 0.f); v.y = fmaxf(v.y, 0.f);
            v.z = fmaxf(v.z, 0.f); v.w = fmaxf(v.w, 0.f);
            *reinterpret_cast<float4*>(&s.wx[(rl0 + r) * INn + lk]) = v;
            *reinterpret_cast<float4*>(&s.awbx[(rl0 + r) * INn + lk]) =
                make_float4(AWc*v.x, AWc*v.y, AWc*v.z, AWc*v.w);
        }
    }

    float state[4] = {0.f, 0.f, 0.f, 0.f};

    __syncthreads();
    asm volatile("barrier.cluster.arrive.aligned;" ::: "memory");
    asm volatile("barrier.cluster.wait.aligned;"   ::: "memory");

    // ---------------- time loop ----------------
    for (int t = 0; t < Tn; t++) {
        const int pb  = (t + 3) & 3;   // buffer holding out(t-1)
        const int cb  = t & 3;         // buffer receiving out(t)
        const int pp  = t & 1;         // plog parity for THIS step's softmax
        const float dtR = DTc * s.Rs[t];
        const float* __restrict__ op = s.o[pb];
        const float* __restrict__ xrow = &x[(t * Bn + b) * INn];

        // --- softmax from pre-aggregated partial logits (8 LDS per lane<7) ---
        float gate, attn_g;
        {
            float L = 0.f;
            if (l < NGn) {
                const float* __restrict__ pl = &s.plog[pp][0][l];
                L = ((pl[0] + pl[8]) + (pl[16] + pl[24]))
                  + ((pl[32] + pl[40]) + (pl[48] + pl[56])) + s.battn[l];
            }
            const float e = (l < NGn) ? __expf(L - 20.f) : 0.f;
            const float ssum = warp_sum(e);
            const float a = __fdividef(e, ssum);
            attn_g = __shfl_sync(0xffffffffu, a, g);
            gate   = __shfl_sync(0xffffffffu, a, l >> 2);
        }

        // --- recurrent + input matvec; op tiles kept in hov for the hebb ---
        float4 hov[4];
        #pragma unroll
        for (int c4 = 0; c4 < 4; c4++)
            hov[c4] = *reinterpret_cast<const float4*>(&op[c4 * 128 + lk]);

        float part[4] = {0.f, 0.f, 0.f, 0.f};
        #pragma unroll
        for (int c4 = 0; c4 < 4; c4++) {
            float4 sv = hov[c4];
            if (c4 == 3) {   // sign boundary at j = 409 (j = 384 + lk + i)
                if (lk + 0 >= 25) sv.x = -sv.x;
                if (lk + 1 >= 25) sv.y = -sv.y;
                if (lk + 2 >= 25) sv.z = -sv.z;
                if (lk + 3 >= 25) sv.w = -sv.w;
            }
            #pragma unroll
            for (int r = 0; r < 4; r++) {
                const float4 wv = *reinterpret_cast<const float4*>(
                    &s.wh[(rl0 + r) * Hn + c4 * 128 + lk]);
                part[r] = fmaf(wv.x, sv.x, part[r]);
                part[r] = fmaf(wv.y, sv.y, part[r]);
                part[r] = fmaf(wv.z, sv.z, part[r]);
                part[r] = fmaf(wv.w, sv.w, part[r]);
            }
        }
        float4 xv = make_float4(0.f, 0.f, 0.f, 0.f);
        if (l < 28) {
            xv = *reinterpret_cast<const float4*>(&xrow[lk]);
            xv.x *= gate; xv.y *= gate; xv.z *= gate; xv.w *= gate;
            #pragma unroll
            for (int r = 0; r < 4; r++) {
                const float4 wxv = *reinterpret_cast<const float4*>(
                    &s.wx[(rl0 + r) * INn + lk]);
                part[r] = fmaf(wxv.x, xv.x, part[r]);
                part[r] = fmaf(wxv.y, xv.y, part[r]);
                part[r] = fmaf(wxv.z, xv.z, part[r]);
                part[r] = fmaf(wxv.w, xv.w, part[r]);
            }
        }

        // --- reduce, state update, out(t) ---
        float base[4];
        #pragma unroll
        for (int r = 0; r < 4; r++) {
            float tot = warp_sum(part[r]);
            const float4 rd = *reinterpret_cast<const float4*>(&s.rowdat[(rl0 + r) * 4]);
            const float orow = op[row0 + r];
            const float osrow = (row0 + r >= En) ? -orow : orow;
            tot = tot - rd.z * osrow + rd.x;        // remove diagonal, add bias
            state[r] = fmaf(AXc, tot, OMAXc * state[r]);
        }
        float tv;
        {
            float st = (l == 0) ? state[0] : (l == 1) ? state[1] : (l == 2) ? state[2] : state[3];
            tv = tanh_relu_fast(st);
            #pragma unroll
            for (int r = 0; r < 4; r++)
                base[r] = dtR * __shfl_sync(0xffffffffu, tv, r);
        }

        // --- push out(t) to all 8 cluster CTAs (lane l -> row l&3, rank l>>2),
        //     plus a plain STS for own rows (local visibility insurance) ---
        {
            const float val = __shfl_sync(0xffffffffu, tv, l & 3);
            st_clu(smem_u32(&s.o[cb][row0 + (l & 3)]), l >> 2, val);
            if (l < 4) s.o[cb][row0 + l] = __shfl_sync(0x0000000fu, tv, l);
        }
        __syncthreads();   // own 64 rows of out(t) visible to all warps

        // --- wa slice update + partial logits for step t+1 (warps 0-6);
        //     readout of t-1 (warps 14/15) ---
        if (w < NGn) {
            const float hbg = dtR * kfb * attn_g;
            const int h0 = rank * 64;
            float p = 0.f;
            #pragma unroll
            for (int c = 0; c < 2; c++) {
                const int col = c * 32 + l;
                const int h = h0 + col;
                const float ot = s.o[cb][h];
                const float hedge = (h < En) ? ot : 0.f;
                float v = fmaf(s.wa[g * 64 + col], OMAWc, s.awba[g * 64 + col]);
                v = fmaf(hbg, hedge, v);
                v = fmaxf(v, 0.f);
                s.wa[g * 64 + col] = v;
                const float osm = (h < EXn) ? ((h < En) ? ot : -ot) : 0.f;
                p = fmaf(v, osm, p);
            }
            p = warp_sum(p);
            if (l < 8) st_clu(smem_u32(&s.plog[pp ^ 1][rank][g]), l, p);
        } else if (t > 0 && (w == 15 || (w == 14 && rank == 0))) {
            const float* __restrict__ ew = (w == 15) ? s.effc : s.effv;
            const int ch = (w == 15) ? rank : 8;
            float p = 0.f;
            #pragma unroll 4
            for (int it = 0; it < 16; it++) {
                const int h = it * 32 + l;
                p = fmaf(ew[h], op[h], p);
            }
            p = warp_sum(p);
            if (l == 0) yout[((t - 1) * Bn + b) * 9 + ch] = p;
        }

        asm volatile("barrier.cluster.arrive.aligned;" ::: "memory");

        // --- plastic wh/wx updates (hidden behind the cluster barrier) ---
        // wh lives in SMEM (thread-private slice: no races); awbh streamed
        // from L2 via __ldcs; op tiles already live in hov.
        const float* __restrict__ gab = &g_awbh[((size_t)b * Hn + row0) * Hn];
        #pragma unroll
        for (int c4 = 0; c4 < 3; c4++) {        // uniform column-half tiles
            const float4 ov = hov[c4];
            #pragma unroll
            for (int r = 0; r < 4; r++) {
                const float cAr = base[r] * ((row0 + r >= En) ? k10 : k00);
                float* __restrict__ wp = &s.wh[(rl0 + r) * Hn + c4 * 128 + lk];
                const float4 wv = *reinterpret_cast<const float4*>(wp);
                const float4 ab = __ldcs(reinterpret_cast<const float4*>(
                    &gab[(size_t)r * Hn + c4 * 128 + lk]));
                float v0 = fmaf(wv.x, OMAWc, ab.x); v0 = fmaf(cAr, ov.x, v0);
                float v1 = fmaf(wv.y, OMAWc, ab.y); v1 = fmaf(cAr, ov.y, v1);
                float v2 = fmaf(wv.z, OMAWc, ab.z); v2 = fmaf(cAr, ov.z, v2);
                float v3 = fmaf(wv.w, OMAWc, ab.w); v3 = fmaf(cAr, ov.w, v3);
                *reinterpret_cast<float4*>(wp) =
                    make_float4(fmaxf(v0, 0.f), fmaxf(v1, 0.f),
                                fmaxf(v2, 0.f), fmaxf(v3, 0.f));
            }
        }
        {   // c4 == 3: mixed column-half tile (boundary at lk + i >= 25)
            const float4 ov = hov[3];
            #pragma unroll
            for (int r = 0; r < 4; r++) {
                const bool rhbr = (row0 + r >= En);
                const float cAr = base[r] * (rhbr ? k10 : k00);
                const float cBr = base[r] * (rhbr ? k11 : k01);
                float* __restrict__ wp = &s.wh[(rl0 + r) * Hn + 384 + lk];
                const float4 wv = *reinterpret_cast<const float4*>(wp);
                const float4 ab = __ldcs(reinterpret_cast<const float4*>(
                    &gab[(size_t)r * Hn + 384 + lk]));
                const float c0 = (lk + 0 >= 25) ? cBr : cAr;
                const float c1 = (lk + 1 >= 25) ? cBr : cAr;
                const float c2 = (lk + 2 >= 25) ? cBr : cAr;
                const float c3 = (lk + 3 >= 25) ? cBr : cAr;
                float v0 = fmaf(wv.x, OMAWc, ab.x); v0 = fmaf(c0, ov.x, v0);
                float v1 = fmaf(wv.y, OMAWc, ab.y); v1 = fmaf(c1, ov.y, v1);
                float v2 = fmaf(wv.z, OMAWc, ab.z); v2 = fmaf(c2, ov.z, v2);
                float v3 = fmaf(wv.w, OMAWc, ab.w); v3 = fmaf(c3, ov.w, v3);
                *reinterpret_cast<float4*>(wp) =
                    make_float4(fmaxf(v0, 0.f), fmaxf(v1, 0.f),
                                fmaxf(v2, 0.f), fmaxf(v3, 0.f));
            }
        }
        // diagonal shadow (lane 0 only; visible next step via its __syncthreads)
        if (l == 0) {
            #pragma unroll
            for (int r = 0; r < 4; r++) {
                const bool rhbr = (row0 + r >= En);
                const float cd = base[r] * (rhbr ? k11 : k00);
                const float awbd = s.rowdat[(rl0 + r) * 4 + 1];
                const float wdv  = s.rowdat[(rl0 + r) * 4 + 2];
                float v = fmaf(wdv, OMAWc, awbd);
                v = fmaf(cd, op[row0 + r], v);
                s.rowdat[(rl0 + r) * 4 + 2] = fmaxf(v, 0.f);
            }
        }
        if (l < 28) {
            #pragma unroll
            for (int r = 0; r < 4; r++) {
                const float4 wxv = *reinterpret_cast<const float4*>(
                    &s.wx[(rl0 + r) * INn + lk]);
                const float4 ab = *reinterpret_cast<const float4*>(
                    &s.awbx[(rl0 + r) * INn + lk]);
                const float cX = base[r] * ((row0 + r >= En) ? kinBt : kinAt);
                float v0 = fmaf(wxv.x, OMAWc, ab.x); v0 = fmaf(cX, xv.x, v0);
                float v1 = fmaf(wxv.y, OMAWc, ab.y); v1 = fmaf(cX, xv.y, v1);
                float v2 = fmaf(wxv.z, OMAWc, ab.z); v2 = fmaf(cX, xv.z, v2);
                float v3 = fmaf(wxv.w, OMAWc, ab.w); v3 = fmaf(cX, xv.w, v3);
                *reinterpret_cast<float4*>(&s.wx[(rl0 + r) * INn + lk]) =
                    make_float4(fmaxf(v0, 0.f), fmaxf(v1, 0.f),
                                fmaxf(v2, 0.f), fmaxf(v3, 0.f));
            }
        }

        asm volatile("barrier.cluster.wait.aligned;" ::: "memory");
    }

    // --- final readout for t = Tn-1 (out(31) sits in buffer (Tn-1)&3 = 3) ---
    if (w == 15 || (w == 14 && rank == 0)) {
        const float* __restrict__ ew = (w == 15) ? s.effc : s.effv;
        const int ch = (w == 15) ? rank : 8;
        float p = 0.f;
        #pragma unroll 4
        for (int it = 0; it < 16; it++) {
            const int h = it * 32 + l;
            p = fmaf(ew[h], s.o[3][h], p);
        }
        p = warp_sum(p);
        if (l == 0) yout[((Tn - 1) * Bn + b) * 9 + ch] = p;
    }
}

extern "C" void kernel_launch(void* const* d_in, const int* in_sizes, int n_in,
                              void* d_out, int out_size) {
    (void)in_sizes; (void)n_in; (void)out_size;
    const size_t smem = sizeof(SM);
    cudaFuncSetAttribute(rnn_kernel, cudaFuncAttributeMaxDynamicSharedMemorySize, (int)smem);
    rnn_kernel<<<Bn * 8, 512, smem>>>(
        (const float*)d_in[0], (const float*)d_in[1], (const float*)d_in[2],
        (const float*)d_in[3], (const float*)d_in[4], (const float*)d_in[5],
        (const float*)d_in[6], (const float*)d_in[7], (const float*)d_in[8],
        (const float*)d_in[9], (float*)d_out);
}

// round 14
// speedup vs baseline: 1.3942x; 1.3942x over previous
#include <cuda_runtime.h>
#include <cstdint>

#define Bn   16
#define Tn   32
#define INn  112
#define Hn   512
#define NGn  7
#define En   409      // int(0.8*512)
#define EXn  410      // H - round(0.2*512)
#define AWc   0.02f
#define OMAWc 0.98f
#define AXc   0.2f
#define OMAXc 0.8f
#define DTc   0.02f

struct __align__(16) SM {
    float awbh[64 * Hn];    // alpha_w * relu(w_h2h) rows of this CTA   131072 B
    float wx[64 * INn];     // plastic input weights (thread-private)    28672 B
    float awbx[64 * INn];   // alpha_w * relu(w_x2h)                     28672 B
    float wa[NGn * 64];     // plastic attn weights, THIS CTA's columns   1792 B
    float awba[NGn * 64];   //                                            1792 B
    float effc[Hn];         // relu(w_h2o[rank]) * exist                  2048 B
    float effv[Hn];         // relu(w_h2v) * exist                        2048 B
    float o[4][Hn];         // out(tau) lives in o[tau & 3]               8192 B
    float rowdat[64 * 4];   // per local row: {bh, awbd, wd, pad}         1024 B
    float plog[2][8][8];    // partial logits [parity][src_rank][group]    512 B
    float battn[8];
    float Rs[Tn];
};

__device__ __forceinline__ float warp_sum(float v) {
    v += __shfl_xor_sync(0xffffffffu, v, 16);
    v += __shfl_xor_sync(0xffffffffu, v, 8);
    v += __shfl_xor_sync(0xffffffffu, v, 4);
    v += __shfl_xor_sync(0xffffffffu, v, 2);
    v += __shfl_xor_sync(0xffffffffu, v, 1);
    return v;
}
__device__ __forceinline__ unsigned int smem_u32(const void* p) {
    unsigned int a;
    asm("{ .reg .u64 t; cvta.to.shared.u64 t, %1; cvt.u32.u64 %0, t; }" : "=r"(a) : "l"(p));
    return a;
}
__device__ __forceinline__ void st_clu(unsigned int laddr, int rank, float v) {
    unsigned int ra;
    asm volatile("mapa.shared::cluster.u32 %0, %1, %2;" : "=r"(ra) : "r"(laddr), "r"(rank));
    asm volatile("st.shared::cluster.f32 [%0], %1;" :: "r"(ra), "f"(v) : "memory");
}
// tanh(relu(x)) with fast exp/div; exact saturation beyond 15
__device__ __forceinline__ float tanh_relu_fast(float x) {
    float xr = fminf(fmaxf(x, 0.f), 15.f);
    float e2 = __expf(2.f * xr);
    return __fdividef(e2 - 1.f, e2 + 1.f);
}

__global__ void __launch_bounds__(512, 1) __cluster_dims__(8, 1, 1)
rnn_kernel(const float* __restrict__ x, const float* __restrict__ R,
           const float* __restrict__ w_x2h, const float* __restrict__ w_h2h,
           const float* __restrict__ b_h2h, const float* __restrict__ w_attn,
           const float* __restrict__ b_attn, const float* __restrict__ w_h2o,
           const float* __restrict__ w_h2v, const float* __restrict__ kappa,
           float* __restrict__ yout)
{
    extern __shared__ __align__(16) char smraw[];
    SM& s = *reinterpret_cast<SM*>(smraw);

    const int tid  = threadIdx.x;
    const int w    = tid >> 5;
    const int l    = tid & 31;
    const int rank = blockIdx.x & 7;
    const int b    = blockIdx.x >> 3;
    const int rl0  = w * 4;            // local row base in CTA (0..60)
    const int row0 = rank * 64 + rl0;  // global row base
    const int lk   = l * 4;            // column base within a 128-block
    const int g    = (w < NGn) ? w : 0;   // attention group for wa warps

    // ---------------- init ----------------
    if (tid < 8)   s.battn[tid] = (tid < NGn) ? b_attn[tid] : 0.f;
    if (tid < Tn)  s.Rs[tid]    = R[tid * Bn + b];
    if (tid < 128) reinterpret_cast<float*>(s.plog)[tid] = 0.f;
    s.o[0][tid] = 0.f; s.o[1][tid] = 0.f;
    s.o[2][tid] = 0.f; s.o[3][tid] = 0.f;   // t=0 reads o[2] (zero) as out(-2)
    if (tid < NGn * 64) {              // this CTA's wa columns
        const int gg = tid >> 6, col = tid & 63;
        const float v = fmaxf(w_attn[gg * Hn + rank * 64 + col], 0.f);
        s.wa[tid] = v; s.awba[tid] = AWc * v;
    }
    s.effc[tid] = (tid < EXn) ? fmaxf(w_h2o[rank * Hn + tid], 0.f) : 0.f;
    s.effv[tid] = (tid < EXn) ? fmaxf(w_h2v[tid], 0.f) : 0.f;
    if (l < 4) {
        const int row = row0 + l;
        const float dv = fmaxf(w_h2h[row * Hn + row], 0.f);
        s.rowdat[(rl0 + l) * 4 + 0] = b_h2h[row];
        s.rowdat[(rl0 + l) * 4 + 1] = AWc * dv;
        s.rowdat[(rl0 + l) * 4 + 2] = dv;
        s.rowdat[(rl0 + l) * 4 + 3] = 0.f;
    }

    // uniform kappa scalars
    const float k00 = kappa[0], k01 = kappa[1], k10 = kappa[2], k11 = kappa[3];
    const float kinAt = kappa[4 + 2 * (l >> 2)];
    const float kinBt = kappa[5 + 2 * (l >> 2)];
    const float kfb = kappa[18 + g / 3];

    float wh[4][16];
    #pragma unroll
    for (int r = 0; r < 4; r++) {
        const int row = row0 + r;
        #pragma unroll
        for (int c4 = 0; c4 < 4; c4++) {
            const int j0 = c4 * 128 + lk;
            float4 v = *reinterpret_cast<const float4*>(&w_h2h[row * Hn + j0]);
            v.x = fmaxf(v.x, 0.f); v.y = fmaxf(v.y, 0.f);
            v.z = fmaxf(v.z, 0.f); v.w = fmaxf(v.w, 0.f);
            wh[r][c4*4+0] = v.x; wh[r][c4*4+1] = v.y;
            wh[r][c4*4+2] = v.z; wh[r][c4*4+3] = v.w;
            *reinterpret_cast<float4*>(&s.awbh[(rl0 + r) * Hn + j0]) =
                make_float4(AWc*v.x, AWc*v.y, AWc*v.z, AWc*v.w);
        }
        if (l < 28) {
            float4 v = *reinterpret_cast<const float4*>(&w_x2h[row * INn + lk]);
            v.x = fmaxf(v.x, 0.f); v.y = fmaxf(v.y, 0.f);
            v.z = fmaxf(v.z, 0.f); v.w = fmaxf(v.w, 0.f);
            *reinterpret_cast<float4*>(&s.wx[(rl0 + r) * INn + lk]) = v;
            *reinterpret_cast<float4*>(&s.awbx[(rl0 + r) * INn + lk]) =
                make_float4(AWc*v.x, AWc*v.y, AWc*v.z, AWc*v.w);
        }
    }

    float state[4] = {0.f, 0.f, 0.f, 0.f};
    float basep[4] = {0.f, 0.f, 0.f, 0.f};          // dtR(t-1) * outn(t-1)
    float4 xvp = make_float4(0.f, 0.f, 0.f, 0.f);   // gated x(t-1)

    __syncthreads();
    asm volatile("barrier.cluster.arrive.aligned;" ::: "memory");
    asm volatile("barrier.cluster.wait.aligned;"   ::: "memory");

    // ---------------- time loop ----------------
    for (int t = 0; t < Tn; t++) {
        const int pb  = (t + 3) & 3;   // buffer holding out(t-1)
        const int qb  = (t + 2) & 3;   // buffer holding out(t-2)
        const int cb  = t & 3;         // buffer receiving out(t)
        const int pp  = t & 1;         // plog parity for THIS step's softmax
        const float dtR = DTc * s.Rs[t];
        const float* __restrict__ op = s.o[pb];
        const float* __restrict__ oq = s.o[qb];
        const float* __restrict__ xrow = &x[(t * Bn + b) * INn];

        // --- softmax from pre-aggregated partial logits (8 LDS per lane<7) ---
        float gate, attn_g;
        {
            float L = 0.f;
            if (l < NGn) {
                const float* __restrict__ pl = &s.plog[pp][0][l];
                L = ((pl[0] + pl[8]) + (pl[16] + pl[24]))
                  + ((pl[32] + pl[40]) + (pl[48] + pl[56])) + s.battn[l];
            }
            const float e = (l < NGn) ? __expf(L - 20.f) : 0.f;
            const float ssum = warp_sum(e);
            const float a = __fdividef(e, ssum);
            attn_g = __shfl_sync(0xffffffffu, a, g);
            gate   = __shfl_sync(0xffffffffu, a, l >> 2);
        }

        // --- FUSED: wh decay+hebb (deferred step t-1) + matvec on out(t-1) ---
        // w(t-1) = max(wh*0.98 + awbh + basep*kappa*out(t-2), 0)
        // part  += w(t-1) * os(t-1)
        float part[4] = {0.f, 0.f, 0.f, 0.f};
        #pragma unroll
        for (int c4 = 0; c4 < 3; c4++) {        // uniform column-half tiles
            const float4 ovp = *reinterpret_cast<const float4*>(&oq[c4 * 128 + lk]);
            const float4 oc  = *reinterpret_cast<const float4*>(&op[c4 * 128 + lk]);
            #pragma unroll
            for (int r = 0; r < 4; r++) {
                const float cAr = basep[r] * ((row0 + r >= En) ? k10 : k00);
                const float4 ab = *reinterpret_cast<const float4*>(
                    &s.awbh[(rl0 + r) * Hn + c4 * 128 + lk]);
                float v0 = fmaf(wh[r][c4*4+0], OMAWc, ab.x); v0 = fmaxf(fmaf(cAr, ovp.x, v0), 0.f);
                float v1 = fmaf(wh[r][c4*4+1], OMAWc, ab.y); v1 = fmaxf(fmaf(cAr, ovp.y, v1), 0.f);
                float v2 = fmaf(wh[r][c4*4+2], OMAWc, ab.z); v2 = fmaxf(fmaf(cAr, ovp.z, v2), 0.f);
                float v3 = fmaf(wh[r][c4*4+3], OMAWc, ab.w); v3 = fmaxf(fmaf(cAr, ovp.w, v3), 0.f);
                wh[r][c4*4+0] = v0; wh[r][c4*4+1] = v1;
                wh[r][c4*4+2] = v2; wh[r][c4*4+3] = v3;
                part[r] = fmaf(v0, oc.x, part[r]);
                part[r] = fmaf(v1, oc.y, part[r]);
                part[r] = fmaf(v2, oc.z, part[r]);
                part[r] = fmaf(v3, oc.w, part[r]);
            }
        }
        {   // c4 == 3: mixed column-half tile (boundary at lk + i >= 25)
            const float4 ovp = *reinterpret_cast<const float4*>(&oq[384 + lk]);
            const float4 oc  = *reinterpret_cast<const float4*>(&op[384 + lk]);
            float4 sc = oc;     // sign-masked for matvec (j >= 409 negative)
            if (lk + 0 >= 25) sc.x = -sc.x;
            if (lk + 1 >= 25) sc.y = -sc.y;
            if (lk + 2 >= 25) sc.z = -sc.z;
            if (lk + 3 >= 25) sc.w = -sc.w;
            #pragma unroll
            for (int r = 0; r < 4; r++) {
                const bool rhbr = (row0 + r >= En);
                const float cAr = basep[r] * (rhbr ? k10 : k00);
                const float cBr = basep[r] * (rhbr ? k11 : k01);
                const float c0 = (lk + 0 >= 25) ? cBr : cAr;
                const float c1 = (lk + 1 >= 25) ? cBr : cAr;
                const float c2 = (lk + 2 >= 25) ? cBr : cAr;
                const float c3 = (lk + 3 >= 25) ? cBr : cAr;
                const float4 ab = *reinterpret_cast<const float4*>(
                    &s.awbh[(rl0 + r) * Hn + 384 + lk]);
                float v0 = fmaf(wh[r][12], OMAWc, ab.x); v0 = fmaxf(fmaf(c0, ovp.x, v0), 0.f);
                float v1 = fmaf(wh[r][13], OMAWc, ab.y); v1 = fmaxf(fmaf(c1, ovp.y, v1), 0.f);
                float v2 = fmaf(wh[r][14], OMAWc, ab.z); v2 = fmaxf(fmaf(c2, ovp.z, v2), 0.f);
                float v3 = fmaf(wh[r][15], OMAWc, ab.w); v3 = fmaxf(fmaf(c3, ovp.w, v3), 0.f);
                wh[r][12] = v0; wh[r][13] = v1; wh[r][14] = v2; wh[r][15] = v3;
                part[r] = fmaf(v0, sc.x, part[r]);
                part[r] = fmaf(v1, sc.y, part[r]);
                part[r] = fmaf(v2, sc.z, part[r]);
                part[r] = fmaf(v3, sc.w, part[r]);
            }
        }
        // --- FUSED: wx decay+hebb (deferred step t-1) + matvec on gated x(t) ---
        if (l < 28) {
            float4 xv = *reinterpret_cast<const float4*>(&xrow[lk]);
            xv.x *= gate; xv.y *= gate; xv.z *= gate; xv.w *= gate;
            #pragma unroll
            for (int r = 0; r < 4; r++) {
                const float cX = basep[r] * ((row0 + r >= En) ? kinBt : kinAt);
                float* __restrict__ wp = &s.wx[(rl0 + r) * INn + lk];
                const float4 wxv = *reinterpret_cast<const float4*>(wp);
                const float4 ab = *reinterpret_cast<const float4*>(
                    &s.awbx[(rl0 + r) * INn + lk]);
                float v0 = fmaf(wxv.x, OMAWc, ab.x); v0 = fmaxf(fmaf(cX, xvp.x, v0), 0.f);
                float v1 = fmaf(wxv.y, OMAWc, ab.y); v1 = fmaxf(fmaf(cX, xvp.y, v1), 0.f);
                float v2 = fmaf(wxv.z, OMAWc, ab.z); v2 = fmaxf(fmaf(cX, xvp.z, v2), 0.f);
                float v3 = fmaf(wxv.w, OMAWc, ab.w); v3 = fmaxf(fmaf(cX, xvp.w, v3), 0.f);
                *reinterpret_cast<float4*>(wp) = make_float4(v0, v1, v2, v3);
                part[r] = fmaf(v0, xv.x, part[r]);
                part[r] = fmaf(v1, xv.y, part[r]);
                part[r] = fmaf(v2, xv.z, part[r]);
                part[r] = fmaf(v3, xv.w, part[r]);
            }
            xvp = xv;   // keep gated x(t) for step t+1's wx update
        }

        // --- reduce, state update, out(t) ---
        #pragma unroll
        for (int r = 0; r < 4; r++) {
            float tot = warp_sum(part[r]);
            const float4 rd = *reinterpret_cast<const float4*>(&s.rowdat[(rl0 + r) * 4]);
            const float orow = op[row0 + r];
            const float osrow = (row0 + r >= En) ? -orow : orow;
            tot = tot - rd.z * osrow + rd.x;        // remove diagonal, add bias
            state[r] = fmaf(AXc, tot, OMAXc * state[r]);
        }
        float tv;
        {
            float st = (l == 0) ? state[0] : (l == 1) ? state[1] : (l == 2) ? state[2] : state[3];
            tv = tanh_relu_fast(st);
            #pragma unroll
            for (int r = 0; r < 4; r++)
                basep[r] = dtR * __shfl_sync(0xffffffffu, tv, r);   // for step t+1
        }

        // --- push out(t) to all 8 cluster CTAs (lane l -> row l&3, rank l>>2),
        //     plus a plain STS for own rows (local visibility insurance) ---
        {
            const float val = __shfl_sync(0xffffffffu, tv, l & 3);
            st_clu(smem_u32(&s.o[cb][row0 + (l & 3)]), l >> 2, val);
            if (l < 4) s.o[cb][row0 + l] = __shfl_sync(0x0000000fu, tv, l);
        }
        __syncthreads();   // own 64 rows of out(t) visible to all warps

        // --- wa slice update + partial logits for step t+1 (warps 0-6);
        //     readout of t-1 (warps 14/15). ALL DSMEM stores PRE-arrive. ---
        if (w < NGn) {
            const float hbg = dtR * kfb * attn_g;
            const int h0 = rank * 64;
            float p = 0.f;
            #pragma unroll
            for (int c = 0; c < 2; c++) {
                const int col = c * 32 + l;
                const int h = h0 + col;
                const float ot = s.o[cb][h];
                const float hedge = (h < En) ? ot : 0.f;
                float v = fmaf(s.wa[g * 64 + col], OMAWc, s.awba[g * 64 + col]);
                v = fmaf(hbg, hedge, v);
                v = fmaxf(v, 0.f);
                s.wa[g * 64 + col] = v;
                const float osm = (h < EXn) ? ((h < En) ? ot : -ot) : 0.f;
                p = fmaf(v, osm, p);
            }
            p = warp_sum(p);
            if (l < 8) st_clu(smem_u32(&s.plog[pp ^ 1][rank][g]), l, p);
        } else if (t > 0 && (w == 15 || (w == 14 && rank == 0))) {
            const float* __restrict__ ew = (w == 15) ? s.effc : s.effv;
            const int ch = (w == 15) ? rank : 8;
            float p = 0.f;
            #pragma unroll 4
            for (int it = 0; it < 16; it++) {
                const int h = it * 32 + l;
                p = fmaf(ew[h], op[h], p);
            }
            p = warp_sum(p);
            if (l == 0) yout[((t - 1) * Bn + b) * 9 + ch] = p;
        }

        asm volatile("barrier.cluster.arrive.aligned;" ::: "memory");

        // --- post-arrive: diagonal shadow only (CTA-local SMEM, no DSMEM) ---
        if (l == 0) {
            #pragma unroll
            for (int r = 0; r < 4; r++) {
                const bool rhbr = (row0 + r >= En);
                const float cd = basep[r] * (rhbr ? k11 : k00);
                const float awbd = s.rowdat[(rl0 + r) * 4 + 1];
                const float wdv  = s.rowdat[(rl0 + r) * 4 + 2];
                float v = fmaf(wdv, OMAWc, awbd);
                v = fmaf(cd, op[row0 + r], v);
                s.rowdat[(rl0 + r) * 4 + 2] = fmaxf(v, 0.f);
            }
        }

        asm volatile("barrier.cluster.wait.aligned;" ::: "memory");
    }

    // --- final readout for t = Tn-1 (out(31) sits in buffer (Tn-1)&3 = 3) ---
    if (w == 15 || (w == 14 && rank == 0)) {
        const float* __restrict__ ew = (w == 15) ? s.effc : s.effv;
        const int ch = (w == 15) ? rank : 8;
        float p = 0.f;
        #pragma unroll 4
        for (int it = 0; it < 16; it++) {
            const int h = it * 32 + l;
            p = fmaf(ew[h], s.o[3][h], p);
        }
        p = warp_sum(p);
        if (l == 0) yout[((Tn - 1) * Bn + b) * 9 + ch] = p;
    }
}

extern "C" void kernel_launch(void* const* d_in, const int* in_sizes, int n_in,
                              void* d_out, int out_size) {
    (void)in_sizes; (void)n_in; (void)out_size;
    const size_t smem = sizeof(SM);
    cudaFuncSetAttribute(rnn_kernel, cudaFuncAttributeMaxDynamicSharedMemorySize, (int)smem);
    rnn_kernel<<<Bn * 8, 512, smem>>>(
        (const float*)d_in[0], (const float*)d_in[1], (const float*)d_in[2],
        (const float*)d_in[3], (const float*)d_in[4], (const float*)d_in[5],
        (const float*)d_in[6], (const float*)d_in[7], (const float*)d_in[8],
        (const float*)d_in[9], (float*)d_out);
}